// round 8
// baseline (speedup 1.0000x reference)
#include <cuda_runtime.h>
#include <math.h>

#define S_FR   16
#define P_TOK  512
#define C_DIM  768
#define H_HEADS 12
#define K_COV  6
#define D_DIM  64
#define N_TOK  8192
#define QKV_N  2304

// Scratch (allocation-free: __device__ globals)
__device__ float g_q[H_HEADS * N_TOK * D_DIM];
__device__ float g_k[H_HEADS * N_TOK * D_DIM];
__device__ float g_v[H_HEADS * N_TOK * D_DIM];
__device__ float g_attn[N_TOK * C_DIM];

__device__ __forceinline__ unsigned f2tf(float f) {
  unsigned u;
  asm("cvt.rna.tf32.f32 %0, %1;" : "=r"(u) : "f"(f));
  return u;
}
__device__ __forceinline__ float ex2(float x) {
  float y;
  asm("ex2.approx.ftz.f32 %0, %1;" : "=f"(y) : "f"(x));
  return y;
}
__device__ __forceinline__ void mma8(float c[4], const unsigned a[4],
                                     const unsigned b[2]) {
  asm volatile(
      "mma.sync.aligned.m16n8k8.row.col.f32.tf32.tf32.f32 "
      "{%0,%1,%2,%3},{%4,%5,%6,%7},{%8,%9},{%0,%1,%2,%3};\n"
      : "+f"(c[0]), "+f"(c[1]), "+f"(c[2]), "+f"(c[3])
      : "r"(a[0]), "r"(a[1]), "r"(a[2]), "r"(a[3]), "r"(b[0]), "r"(b[1]));
}
__device__ __forceinline__ uint4 tf4(float4 v) {
  uint4 t;
  t.x = f2tf(v.x); t.y = f2tf(v.y); t.z = f2tf(v.z); t.w = f2tf(v.w);
  return t;
}
__device__ __forceinline__ uint4 tf4s(float4 v, float c) {
  uint4 t;
  t.x = f2tf(v.x * c); t.y = f2tf(v.y * c);
  t.z = f2tf(v.z * c); t.w = f2tf(v.w * c);
  return t;
}

// ---------------------------------------------------------------------------
// TF32 mma GEMM (unchanged, round-3 proven): C = A[M,768]*B[768,N] + bias
// ---------------------------------------------------------------------------
#define AST 20
#define BST 136

template <int MODE>
__global__ __launch_bounds__(256) void gemm_mma(
    const float* __restrict__ A, const float* __restrict__ B,
    const float* __restrict__ bias, float* __restrict__ Cout, int Ncols) {
  __shared__ unsigned As[128 * AST];
  __shared__ unsigned Bs[16 * BST];
  const int tid = threadIdx.x;
  const int warp = tid >> 5, lane = tid & 31;
  const int gid = lane >> 2, tig = lane & 3;
  const int wm = warp >> 2, wn = warp & 3;
  const int bn = blockIdx.x, bm = blockIdx.y;

  const float* Ap = (MODE == 1) ? (const float*)g_attn : A;
  const float* Ab = Ap + (size_t)(bm * 128) * C_DIM;
  const float* Bb = B + bn * 128;

  const int arow = tid >> 2, acol = (tid & 3) << 2;
  const int brow = tid >> 5, bcol = (tid & 31) << 2;

  float acc[16][4];
#pragma unroll
  for (int i = 0; i < 16; i++)
#pragma unroll
    for (int j = 0; j < 4; j++) acc[i][j] = 0.f;

  float4 pa0, pa1, pb0, pb1;
  pa0 = *(const float4*)&Ab[(size_t)arow * C_DIM + acol];
  pa1 = *(const float4*)&Ab[(size_t)(arow + 64) * C_DIM + acol];
  pb0 = *(const float4*)&Bb[(size_t)brow * Ncols + bcol];
  pb1 = *(const float4*)&Bb[(size_t)(brow + 8) * Ncols + bcol];

  const int NT = C_DIM / 16;
  for (int t = 0; t < NT; t++) {
    __syncthreads();
    *(uint4*)&As[arow * AST + acol] = tf4(pa0);
    *(uint4*)&As[(arow + 64) * AST + acol] = tf4(pa1);
    *(uint4*)&Bs[brow * BST + bcol] = tf4(pb0);
    *(uint4*)&Bs[(brow + 8) * BST + bcol] = tf4(pb1);
    __syncthreads();

    if (t + 1 < NT) {
      const int k0 = (t + 1) * 16;
      pa0 = *(const float4*)&Ab[(size_t)arow * C_DIM + k0 + acol];
      pa1 = *(const float4*)&Ab[(size_t)(arow + 64) * C_DIM + k0 + acol];
      pb0 = *(const float4*)&Bb[(size_t)(k0 + brow) * Ncols + bcol];
      pb1 = *(const float4*)&Bb[(size_t)(k0 + brow + 8) * Ncols + bcol];
    }

#pragma unroll
    for (int ks = 0; ks < 2; ks++) {
      const int k = ks * 8;
      unsigned af[4][4], bf[4][2];
#pragma unroll
      for (int mt = 0; mt < 4; mt++) {
        const int m = wm * 64 + mt * 16 + gid;
        af[mt][0] = As[m * AST + k + tig];
        af[mt][1] = As[(m + 8) * AST + k + tig];
        af[mt][2] = As[m * AST + k + tig + 4];
        af[mt][3] = As[(m + 8) * AST + k + tig + 4];
      }
#pragma unroll
      for (int nt = 0; nt < 4; nt++) {
        const int n = wn * 32 + nt * 8 + gid;
        bf[nt][0] = Bs[(k + tig) * BST + n];
        bf[nt][1] = Bs[(k + tig + 4) * BST + n];
      }
#pragma unroll
      for (int mt = 0; mt < 4; mt++)
#pragma unroll
        for (int nt = 0; nt < 4; nt++) mma8(acc[mt * 4 + nt], af[mt], bf[nt]);
    }
  }

#pragma unroll
  for (int mt = 0; mt < 4; mt++) {
#pragma unroll
    for (int nt = 0; nt < 4; nt++) {
      const int row = bm * 128 + wm * 64 + mt * 16 + gid;
      const int col = bn * 128 + wn * 32 + nt * 8 + 2 * tig;
      const float b0 = bias[col], b1 = bias[col + 1];
      float2 lo, hi;
      lo.x = acc[mt * 4 + nt][0] + b0;
      lo.y = acc[mt * 4 + nt][1] + b1;
      hi.x = acc[mt * 4 + nt][2] + b0;
      hi.y = acc[mt * 4 + nt][3] + b1;
      if (MODE == 0) {
        const int which = col / C_DIM;
        const int rem = col - which * C_DIM;
        const int h = rem >> 6, d = rem & 63;
        float* dst = (which == 0) ? g_q : (which == 1 ? g_k : g_v);
        *(float2*)&dst[((size_t)h * N_TOK + row) * D_DIM + d] = lo;
        *(float2*)&dst[((size_t)h * N_TOK + row + 8) * D_DIM + d] = hi;
      } else {
        *(float2*)&Cout[(size_t)row * C_DIM + col] = lo;
        *(float2*)&Cout[(size_t)(row + 8) * C_DIM + col] = hi;
      }
    }
  }
}

// ---------------------------------------------------------------------------
// TF32 mma flash attention v4:
//  - 4 warps x 32 q-rows, 128-q CTA, KEY TILE 32 -> smem 69.5KB -> occ 3
//    (12 warps/SM: the latency-hiding lever; both pipes were at ~45%)
//  - b-frag reuse x2 kept; K/V register prefetch kept
//  - P buffer 128x32 (stride 36, conflict-free a-frag banks)
// ---------------------------------------------------------------------------
#define QST 68
#define KST 68
#define VST 72
#define PST 36
#define KT  32
#define NT32 ((K_COV * P_TOK) / KT)   // 96
#define ATTN_SMEM ((128 * QST + KT * KST + KT * VST + 128 * PST) * 4)

__global__ __launch_bounds__(128, 3) void attn_kernel(
    const int* __restrict__ covis) {
  extern __shared__ unsigned sm[];
  unsigned* Qs = sm;                    // [128][QST]
  unsigned* Ks = Qs + 128 * QST;        // [32][KST]  key-major
  unsigned* Vs = Ks + KT * KST;         // [32][VST]  key-major
  unsigned* Ps = Vs + KT * VST;         // [128][PST]

  const int tid = threadIdx.x;
  const int warp = tid >> 5, lane = tid & 31;
  const int gid = lane >> 2, tig = lane & 3;
  const int qt = blockIdx.x, h = blockIdx.y, f = blockIdx.z;

  // K/V staging coords: thread covers rows krow+8j (j=0..3), 4 cols
  const int krow = tid >> 4;            // 0..7
  const int kc4 = (tid & 15) << 2;      // 0,4,...,60

  const float CS = 0.18033688011f;      // 0.125 * log2(e)

  // Stage Q tile (fp32 -> tf32, pre-scaled): 128 x 64
  const float* qptr = g_q + ((size_t)h * N_TOK + f * P_TOK + qt * 128) * D_DIM;
#pragma unroll
  for (int j = 0; j < 16; j++) {
    int i = j * 128 + tid;
    int row = i >> 4, c4 = (i & 15) << 2;
    *(uint4*)&Qs[row * QST + c4] =
        tf4s(*(const float4*)&qptr[row * D_DIM + c4], CS);
  }

  float o[2][8][4];
#pragma unroll
  for (int mt = 0; mt < 2; mt++)
#pragma unroll
    for (int nb = 0; nb < 8; nb++)
#pragma unroll
      for (int j = 0; j < 4; j++) o[mt][nb][j] = 0.f;
  float mrow[2][2], lrow[2][2];
#pragma unroll
  for (int mt = 0; mt < 2; mt++) {
    mrow[mt][0] = -INFINITY; mrow[mt][1] = -INFINITY;
    lrow[mt][0] = 0.f; lrow[mt][1] = 0.f;
  }

  const unsigned* Qw = Qs + warp * 32 * QST;
  unsigned* Pw = Ps + warp * 32 * PST;

  const size_t hbase = (size_t)h * N_TOK;

  // Prologue: prefetch K(0) (first 32 keys of first covisible frame)
  float4 kreg[4], vreg[4];
  {
    const int frame = covis[f * K_COV];
    const float* kp = g_k + (hbase + frame * P_TOK) * D_DIM;
#pragma unroll
    for (int j = 0; j < 4; j++)
      kreg[j] = *(const float4*)&kp[(j * 8 + krow) * D_DIM + kc4];
  }

  for (int t = 0; t < NT32; t++) {
    const int frame = covis[f * K_COV + (t >> 4)];
    const int off = (t & 15) << 5;

    // ---- stage K(t) from prefetch regs ----
    // (safe: all warps' QK(t-1) reads of Ks precede last tile's 2nd barrier)
#pragma unroll
    for (int j = 0; j < 4; j++)
      *(uint4*)&Ks[(j * 8 + krow) * KST + kc4] = tf4(kreg[j]);
    __syncthreads();

    // ---- issue V(t) LDG; lands during QK compute ----
    {
      const float* vp = g_v + (hbase + frame * P_TOK + off) * D_DIM;
#pragma unroll
      for (int j = 0; j < 4; j++)
        vreg[j] = *(const float4*)&vp[(j * 8 + krow) * D_DIM + kc4];
    }

    // ---- S = Q K^T : warp computes 32x32 (2 m-tiles share b-frags) ----
    float s[2][4][4];
#pragma unroll
    for (int mt = 0; mt < 2; mt++)
#pragma unroll
      for (int nb = 0; nb < 4; nb++)
#pragma unroll
        for (int j = 0; j < 4; j++) s[mt][nb][j] = 0.f;
#pragma unroll
    for (int ks = 0; ks < 8; ks++) {
      unsigned a[2][4];
#pragma unroll
      for (int mt = 0; mt < 2; mt++) {
        const int r = mt * 16 + gid;
        a[mt][0] = Qw[r * QST + ks * 8 + tig];
        a[mt][1] = Qw[(r + 8) * QST + ks * 8 + tig];
        a[mt][2] = Qw[r * QST + ks * 8 + tig + 4];
        a[mt][3] = Qw[(r + 8) * QST + ks * 8 + tig + 4];
      }
#pragma unroll
      for (int nb = 0; nb < 4; nb++) {
        unsigned b[2];
        b[0] = Ks[(nb * 8 + gid) * KST + ks * 8 + tig];
        b[1] = Ks[(nb * 8 + gid) * KST + ks * 8 + tig + 4];
        mma8(s[0][nb], a[0], b);
        mma8(s[1][nb], a[1], b);
      }
    }

    // ---- online softmax (base-2; Q pre-scaled) + P store (32 cols) ----
#pragma unroll
    for (int mt = 0; mt < 2; mt++) {
      float mx0 = -INFINITY, mx1 = -INFINITY;
#pragma unroll
      for (int nb = 0; nb < 4; nb++) {
        mx0 = fmaxf(mx0, fmaxf(s[mt][nb][0], s[mt][nb][1]));
        mx1 = fmaxf(mx1, fmaxf(s[mt][nb][2], s[mt][nb][3]));
      }
      mx0 = fmaxf(mx0, __shfl_xor_sync(0xffffffffu, mx0, 1));
      mx0 = fmaxf(mx0, __shfl_xor_sync(0xffffffffu, mx0, 2));
      mx1 = fmaxf(mx1, __shfl_xor_sync(0xffffffffu, mx1, 1));
      mx1 = fmaxf(mx1, __shfl_xor_sync(0xffffffffu, mx1, 2));
      const float nm0 = fmaxf(mrow[mt][0], mx0);
      const float nm1 = fmaxf(mrow[mt][1], mx1);
      const float rf0 = ex2(mrow[mt][0] - nm0);
      const float rf1 = ex2(mrow[mt][1] - nm1);
      mrow[mt][0] = nm0; mrow[mt][1] = nm1;

      float sum0 = 0.f, sum1 = 0.f;
      const int r = mt * 16 + gid;
#pragma unroll
      for (int nb = 0; nb < 4; nb++) {
        float p0 = ex2(s[mt][nb][0] - nm0);
        float p1 = ex2(s[mt][nb][1] - nm0);
        float p2 = ex2(s[mt][nb][2] - nm1);
        float p3 = ex2(s[mt][nb][3] - nm1);
        sum0 += p0 + p1;
        sum1 += p2 + p3;
        uint2 u01; u01.x = f2tf(p0); u01.y = f2tf(p1);
        uint2 u23; u23.x = f2tf(p2); u23.y = f2tf(p3);
        *(uint2*)&Pw[r * PST + nb * 8 + 2 * tig] = u01;
        *(uint2*)&Pw[(r + 8) * PST + nb * 8 + 2 * tig] = u23;
      }
      sum0 += __shfl_xor_sync(0xffffffffu, sum0, 1);
      sum0 += __shfl_xor_sync(0xffffffffu, sum0, 2);
      sum1 += __shfl_xor_sync(0xffffffffu, sum1, 1);
      sum1 += __shfl_xor_sync(0xffffffffu, sum1, 2);
      lrow[mt][0] = lrow[mt][0] * rf0 + sum0;
      lrow[mt][1] = lrow[mt][1] * rf1 + sum1;
#pragma unroll
      for (int nb = 0; nb < 8; nb++) {
        o[mt][nb][0] *= rf0; o[mt][nb][1] *= rf0;
        o[mt][nb][2] *= rf1; o[mt][nb][3] *= rf1;
      }
    }

    // ---- stage V(t) (prev PV reads precede this tile's 1st barrier) ----
#pragma unroll
    for (int j = 0; j < 4; j++)
      *(uint4*)&Vs[(j * 8 + krow) * VST + kc4] = tf4(vreg[j]);
    __syncthreads();

    // ---- issue K(t+1) LDG; lands during PV compute ----
    if (t + 1 < NT32) {
      const int nfr = covis[f * K_COV + ((t + 1) >> 4)];
      const int noff = ((t + 1) & 15) << 5;
      const float* kp = g_k + (hbase + nfr * P_TOK + noff) * D_DIM;
#pragma unroll
      for (int j = 0; j < 4; j++)
        kreg[j] = *(const float4*)&kp[(j * 8 + krow) * D_DIM + kc4];
    }

    // ---- O += P V (2 m-tiles share V b-frags; k-dim = 32 keys) ----
#pragma unroll
    for (int ks = 0; ks < 4; ks++) {
      unsigned a[2][4];
#pragma unroll
      for (int mt = 0; mt < 2; mt++) {
        const int r = mt * 16 + gid;
        a[mt][0] = Pw[r * PST + ks * 8 + tig];
        a[mt][1] = Pw[(r + 8) * PST + ks * 8 + tig];
        a[mt][2] = Pw[r * PST + ks * 8 + tig + 4];
        a[mt][3] = Pw[(r + 8) * PST + ks * 8 + tig + 4];
      }
#pragma unroll
      for (int nb = 0; nb < 8; nb++) {
        unsigned b[2];
        b[0] = Vs[(ks * 8 + tig) * VST + nb * 8 + gid];
        b[1] = Vs[(ks * 8 + tig + 4) * VST + nb * 8 + gid];
        mma8(o[0][nb], a[0], b);
        mma8(o[1][nb], a[1], b);
      }
    }
    // (no syncwarp needed: next P write is after next tile's __syncthreads)
  }

  // ---- finalize: O / l, write [N, H*D] ----
#pragma unroll
  for (int mt = 0; mt < 2; mt++) {
    const float inv0 = 1.f / lrow[mt][0], inv1 = 1.f / lrow[mt][1];
    const int tok0 = f * P_TOK + qt * 128 + warp * 32 + mt * 16 + gid;
    float* op0 = g_attn + (size_t)tok0 * C_DIM + h * D_DIM;
    float* op1 = op0 + 8 * C_DIM;
#pragma unroll
    for (int nb = 0; nb < 8; nb++) {
      float2 w0, w1;
      w0.x = o[mt][nb][0] * inv0; w0.y = o[mt][nb][1] * inv0;
      w1.x = o[mt][nb][2] * inv1; w1.y = o[mt][nb][3] * inv1;
      *(float2*)&op0[nb * 8 + 2 * tig] = w0;
      *(float2*)&op1[nb * 8 + 2 * tig] = w1;
    }
  }
}

// ---------------------------------------------------------------------------
extern "C" void kernel_launch(void* const* d_in, const int* in_sizes, int n_in,
                              void* d_out, int out_size) {
  const float* x     = (const float*)d_in[0];
  const float* Wqkv  = (const float*)d_in[1];
  const float* bqkv  = (const float*)d_in[2];
  const float* Wproj = (const float*)d_in[3];
  const float* bproj = (const float*)d_in[4];
  const int*   covis = (const int*)d_in[5];
  float* out = (float*)d_out;
  (void)in_sizes; (void)n_in; (void)out_size;

  cudaFuncSetAttribute(attn_kernel, cudaFuncAttributeMaxDynamicSharedMemorySize,
                       ATTN_SMEM);

  gemm_mma<0><<<dim3(QKV_N / 128, N_TOK / 128), 256>>>(x, Wqkv, bqkv,
                                                       nullptr, QKV_N);
  attn_kernel<<<dim3(P_TOK / 128, H_HEADS, S_FR), 128, ATTN_SMEM>>>(covis);
  gemm_mma<1><<<dim3(C_DIM / 128, N_TOK / 128), 256>>>(nullptr, Wproj, bproj,
                                                       out, C_DIM);
}

// round 9
// speedup vs baseline: 1.0889x; 1.0889x over previous
#include <cuda_runtime.h>
#include <math.h>

#define S_FR   16
#define P_TOK  512
#define C_DIM  768
#define H_HEADS 12
#define K_COV  6
#define D_DIM  64
#define N_TOK  8192
#define QKV_N  2304

// Scratch (allocation-free: __device__ globals)
__device__ float g_q[H_HEADS * N_TOK * D_DIM];
__device__ float g_k[H_HEADS * N_TOK * D_DIM];
__device__ float g_v[H_HEADS * N_TOK * D_DIM];
__device__ float g_attn[N_TOK * C_DIM];

__device__ __forceinline__ unsigned f2tf(float f) {
  unsigned u;
  asm("cvt.rna.tf32.f32 %0, %1;" : "=r"(u) : "f"(f));
  return u;
}
__device__ __forceinline__ float ex2(float x) {
  float y;
  asm("ex2.approx.ftz.f32 %0, %1;" : "=f"(y) : "f"(x));
  return y;
}
__device__ __forceinline__ void mma8(float c[4], const unsigned a[4],
                                     const unsigned b[2]) {
  asm volatile(
      "mma.sync.aligned.m16n8k8.row.col.f32.tf32.tf32.f32 "
      "{%0,%1,%2,%3},{%4,%5,%6,%7},{%8,%9},{%0,%1,%2,%3};\n"
      : "+f"(c[0]), "+f"(c[1]), "+f"(c[2]), "+f"(c[3])
      : "r"(a[0]), "r"(a[1]), "r"(a[2]), "r"(a[3]), "r"(b[0]), "r"(b[1]));
}
__device__ __forceinline__ uint4 tf4(float4 v) {
  uint4 t;
  t.x = f2tf(v.x); t.y = f2tf(v.y); t.z = f2tf(v.z); t.w = f2tf(v.w);
  return t;
}
__device__ __forceinline__ uint4 tf4s(float4 v, float c) {
  uint4 t;
  t.x = f2tf(v.x * c); t.y = f2tf(v.y * c);
  t.z = f2tf(v.z * c); t.w = f2tf(v.w * c);
  return t;
}
__device__ __forceinline__ unsigned smem_u32(const void* p) {
  unsigned a;
  asm("{ .reg .u64 t; cvta.to.shared.u64 t, %1; cvt.u32.u64 %0, t; }"
      : "=r"(a) : "l"(p));
  return a;
}
__device__ __forceinline__ void cp16(unsigned smem, const void* gmem) {
  asm volatile("cp.async.cg.shared.global [%0], [%1], 16;"
               :: "r"(smem), "l"(gmem) : "memory");
}

// ---------------------------------------------------------------------------
// TF32 mma GEMM: C = A[M,768]*B[768,N] + bias
// MODE 0: scatter into q/k/v [H,N,D] — k and v values pre-rounded to tf32
// (rna) so attention can cp.async them raw and the mma truncation is a no-op.
// ---------------------------------------------------------------------------
#define AST 20
#define BST 136

template <int MODE>
__global__ __launch_bounds__(256) void gemm_mma(
    const float* __restrict__ A, const float* __restrict__ B,
    const float* __restrict__ bias, float* __restrict__ Cout, int Ncols) {
  __shared__ unsigned As[128 * AST];
  __shared__ unsigned Bs[16 * BST];
  const int tid = threadIdx.x;
  const int warp = tid >> 5, lane = tid & 31;
  const int gid = lane >> 2, tig = lane & 3;
  const int wm = warp >> 2, wn = warp & 3;
  const int bn = blockIdx.x, bm = blockIdx.y;

  const float* Ap = (MODE == 1) ? (const float*)g_attn : A;
  const float* Ab = Ap + (size_t)(bm * 128) * C_DIM;
  const float* Bb = B + bn * 128;

  const int arow = tid >> 2, acol = (tid & 3) << 2;
  const int brow = tid >> 5, bcol = (tid & 31) << 2;

  float acc[16][4];
#pragma unroll
  for (int i = 0; i < 16; i++)
#pragma unroll
    for (int j = 0; j < 4; j++) acc[i][j] = 0.f;

  float4 pa0, pa1, pb0, pb1;
  pa0 = *(const float4*)&Ab[(size_t)arow * C_DIM + acol];
  pa1 = *(const float4*)&Ab[(size_t)(arow + 64) * C_DIM + acol];
  pb0 = *(const float4*)&Bb[(size_t)brow * Ncols + bcol];
  pb1 = *(const float4*)&Bb[(size_t)(brow + 8) * Ncols + bcol];

  const int NT = C_DIM / 16;
  for (int t = 0; t < NT; t++) {
    __syncthreads();
    *(uint4*)&As[arow * AST + acol] = tf4(pa0);
    *(uint4*)&As[(arow + 64) * AST + acol] = tf4(pa1);
    *(uint4*)&Bs[brow * BST + bcol] = tf4(pb0);
    *(uint4*)&Bs[(brow + 8) * BST + bcol] = tf4(pb1);
    __syncthreads();

    if (t + 1 < NT) {
      const int k0 = (t + 1) * 16;
      pa0 = *(const float4*)&Ab[(size_t)arow * C_DIM + k0 + acol];
      pa1 = *(const float4*)&Ab[(size_t)(arow + 64) * C_DIM + k0 + acol];
      pb0 = *(const float4*)&Bb[(size_t)(k0 + brow) * Ncols + bcol];
      pb1 = *(const float4*)&Bb[(size_t)(k0 + brow + 8) * Ncols + bcol];
    }

#pragma unroll
    for (int ks = 0; ks < 2; ks++) {
      const int k = ks * 8;
      unsigned af[4][4], bf[4][2];
#pragma unroll
      for (int mt = 0; mt < 4; mt++) {
        const int m = wm * 64 + mt * 16 + gid;
        af[mt][0] = As[m * AST + k + tig];
        af[mt][1] = As[(m + 8) * AST + k + tig];
        af[mt][2] = As[m * AST + k + tig + 4];
        af[mt][3] = As[(m + 8) * AST + k + tig + 4];
      }
#pragma unroll
      for (int nt = 0; nt < 4; nt++) {
        const int n = wn * 32 + nt * 8 + gid;
        bf[nt][0] = Bs[(k + tig) * BST + n];
        bf[nt][1] = Bs[(k + tig + 4) * BST + n];
      }
#pragma unroll
      for (int mt = 0; mt < 4; mt++)
#pragma unroll
        for (int nt = 0; nt < 4; nt++) mma8(acc[mt * 4 + nt], af[mt], bf[nt]);
    }
  }

#pragma unroll
  for (int mt = 0; mt < 4; mt++) {
#pragma unroll
    for (int nt = 0; nt < 4; nt++) {
      const int row = bm * 128 + wm * 64 + mt * 16 + gid;
      const int col = bn * 128 + wn * 32 + nt * 8 + 2 * tig;
      const float b0 = bias[col], b1 = bias[col + 1];
      float2 lo, hi;
      lo.x = acc[mt * 4 + nt][0] + b0;
      lo.y = acc[mt * 4 + nt][1] + b1;
      hi.x = acc[mt * 4 + nt][2] + b0;
      hi.y = acc[mt * 4 + nt][3] + b1;
      if (MODE == 0) {
        const int which = col / C_DIM;
        const int rem = col - which * C_DIM;
        const int h = rem >> 6, d = rem & 63;
        float* dst = (which == 0) ? g_q : (which == 1 ? g_k : g_v);
        if (which != 0) {  // k/v: pre-round to tf32 (rna) for raw cp.async
          lo.x = __uint_as_float(f2tf(lo.x));
          lo.y = __uint_as_float(f2tf(lo.y));
          hi.x = __uint_as_float(f2tf(hi.x));
          hi.y = __uint_as_float(f2tf(hi.y));
        }
        *(float2*)&dst[((size_t)h * N_TOK + row) * D_DIM + d] = lo;
        *(float2*)&dst[((size_t)h * N_TOK + row + 8) * D_DIM + d] = hi;
      } else {
        *(float2*)&Cout[(size_t)row * C_DIM + col] = lo;
        *(float2*)&Cout[(size_t)(row + 8) * C_DIM + col] = hi;
      }
    }
  }
}

// ---------------------------------------------------------------------------
// TF32 mma flash attention v5:
//  - 4 warps x 32 q-rows, 128-q CTA, 64-key tiles (round-7 shape), occ 2
//  - Q a-fragments hoisted to registers (loop-invariant); P overlays Qs smem
//  - K/V double-buffered; staged by cp.async (zero regs, off critical path)
//  - ONE __syncthreads per tile (was 2)
// ---------------------------------------------------------------------------
#define QST 68   // Qs/P stride: a-frag bank = 4*gid+tig, conflict-free
#define KST 68   // Ks stride:   k b-frag bank = 4*gid+tig, conflict-free
#define VST 72   // Vs stride:   v b-frag bank = 8*tig+gid, conflict-free
#define NTILE ((K_COV * P_TOK) / 64)   // 48
#define ATTN_SMEM ((128 * QST + 2 * 64 * KST + 2 * 64 * VST) * 4)

__global__ __launch_bounds__(128, 2) void attn_kernel(
    const int* __restrict__ covis) {
  extern __shared__ unsigned sm[];
  unsigned* Qs = sm;                       // [128][QST]; becomes P after qf
  unsigned* Ks = Qs + 128 * QST;           // [2][64][KST] key-major
  unsigned* Vs = Ks + 2 * 64 * KST;        // [2][64][VST] key-major

  const int tid = threadIdx.x;
  const int warp = tid >> 5, lane = tid & 31;
  const int gid = lane >> 2, tig = lane & 3;
  const int qt = blockIdx.x, h = blockIdx.y, f = blockIdx.z;

  const unsigned ks_base = smem_u32(Ks);
  const unsigned vs_base = smem_u32(Vs);

  // K/V staging coords: thread covers rows j*8+krow (j=0..7), 4 cols
  const int krow = tid >> 4;               // 0..7
  const int kc4 = (tid & 15) << 2;         // 0,4,...,60

  const float CS = 0.18033688011f;         // 0.125 * log2(e)
  const size_t hbase = (size_t)h * N_TOK;

  // ---- stage Q (fp32 -> tf32, pre-scaled) ----
  const float* qptr = g_q + (hbase + f * P_TOK + qt * 128) * D_DIM;
#pragma unroll
  for (int j = 0; j < 16; j++) {
    int i = j * 128 + tid;
    int row = i >> 4, c4 = (i & 15) << 2;
    *(uint4*)&Qs[row * QST + c4] =
        tf4s(*(const float4*)&qptr[row * D_DIM + c4], CS);
  }

  // ---- cp.async tile 0 into buffer 0 ----
  {
    const int frame = covis[f * K_COV];
    const float* kp = g_k + (hbase + frame * P_TOK) * D_DIM;
    const float* vp = g_v + (hbase + frame * P_TOK) * D_DIM;
#pragma unroll
    for (int j = 0; j < 8; j++) {
      const int row = j * 8 + krow;
      cp16(ks_base + (row * KST + kc4) * 4, &kp[row * D_DIM + kc4]);
      cp16(vs_base + (row * VST + kc4) * 4, &vp[row * D_DIM + kc4]);
    }
    asm volatile("cp.async.commit_group;" ::: "memory");
    asm volatile("cp.async.wait_group 0;" ::: "memory");
  }
  __syncthreads();

  // ---- hoist Q a-fragments into registers (loop-invariant) ----
  const unsigned* Qw = Qs + warp * 32 * QST;
  unsigned qf[2][8][4];
#pragma unroll
  for (int ks = 0; ks < 8; ks++)
#pragma unroll
    for (int mt = 0; mt < 2; mt++) {
      const int r = mt * 16 + gid;
      qf[mt][ks][0] = Qw[r * QST + ks * 8 + tig];
      qf[mt][ks][1] = Qw[(r + 8) * QST + ks * 8 + tig];
      qf[mt][ks][2] = Qw[r * QST + ks * 8 + tig + 4];
      qf[mt][ks][3] = Qw[(r + 8) * QST + ks * 8 + tig + 4];
    }
  unsigned* Pw = (unsigned*)Qw;  // P overlays this warp's (now dead) Q rows

  float o[2][8][4];
#pragma unroll
  for (int mt = 0; mt < 2; mt++)
#pragma unroll
    for (int nb = 0; nb < 8; nb++)
#pragma unroll
      for (int j = 0; j < 4; j++) o[mt][nb][j] = 0.f;
  float mrow[2][2], lrow[2][2];
#pragma unroll
  for (int mt = 0; mt < 2; mt++) {
    mrow[mt][0] = -INFINITY; mrow[mt][1] = -INFINITY;
    lrow[mt][0] = 0.f; lrow[mt][1] = 0.f;
  }

  for (int t = 0; t < NTILE; t++) {
    const int b = t & 1;
    const unsigned* Kb = Ks + b * 64 * KST;
    const unsigned* Vb = Vs + b * 64 * VST;

    // ---- cp.async tile t+1 into buffer b^1 (readers done at last sync) ----
    if (t + 1 < NTILE) {
      const int u = t + 1;
      const int frame = covis[f * K_COV + (u >> 3)];
      const int off = (u & 7) << 6;
      const float* kp = g_k + (hbase + frame * P_TOK + off) * D_DIM;
      const float* vp = g_v + (hbase + frame * P_TOK + off) * D_DIM;
      const unsigned kb = ks_base + (b ^ 1) * (64 * KST * 4);
      const unsigned vb = vs_base + (b ^ 1) * (64 * VST * 4);
#pragma unroll
      for (int j = 0; j < 8; j++) {
        const int row = j * 8 + krow;
        cp16(kb + (row * KST + kc4) * 4, &kp[row * D_DIM + kc4]);
        cp16(vb + (row * VST + kc4) * 4, &vp[row * D_DIM + kc4]);
      }
      asm volatile("cp.async.commit_group;" ::: "memory");
    }

    // ---- S = Q K^T : warp computes 32x64 (2 m-tiles share b-frags) ----
    float s[2][8][4];
#pragma unroll
    for (int mt = 0; mt < 2; mt++)
#pragma unroll
      for (int nb = 0; nb < 8; nb++)
#pragma unroll
        for (int j = 0; j < 4; j++) s[mt][nb][j] = 0.f;
#pragma unroll
    for (int ks = 0; ks < 8; ks++) {
#pragma unroll
      for (int nb = 0; nb < 8; nb++) {
        unsigned bb[2];
        bb[0] = Kb[(nb * 8 + gid) * KST + ks * 8 + tig];
        bb[1] = Kb[(nb * 8 + gid) * KST + ks * 8 + tig + 4];
        mma8(s[0][nb], qf[0][ks], bb);
        mma8(s[1][nb], qf[1][ks], bb);
      }
    }

    // ---- online softmax (base-2; Q pre-scaled) + P store ----
#pragma unroll
    for (int mt = 0; mt < 2; mt++) {
      float mx0 = -INFINITY, mx1 = -INFINITY;
#pragma unroll
      for (int nb = 0; nb < 8; nb++) {
        mx0 = fmaxf(mx0, fmaxf(s[mt][nb][0], s[mt][nb][1]));
        mx1 = fmaxf(mx1, fmaxf(s[mt][nb][2], s[mt][nb][3]));
      }
      mx0 = fmaxf(mx0, __shfl_xor_sync(0xffffffffu, mx0, 1));
      mx0 = fmaxf(mx0, __shfl_xor_sync(0xffffffffu, mx0, 2));
      mx1 = fmaxf(mx1, __shfl_xor_sync(0xffffffffu, mx1, 1));
      mx1 = fmaxf(mx1, __shfl_xor_sync(0xffffffffu, mx1, 2));
      const float nm0 = fmaxf(mrow[mt][0], mx0);
      const float nm1 = fmaxf(mrow[mt][1], mx1);
      const float rf0 = ex2(mrow[mt][0] - nm0);
      const float rf1 = ex2(mrow[mt][1] - nm1);
      mrow[mt][0] = nm0; mrow[mt][1] = nm1;

      float sum0 = 0.f, sum1 = 0.f;
      const int r = mt * 16 + gid;
#pragma unroll
      for (int nb = 0; nb < 8; nb++) {
        float p0 = ex2(s[mt][nb][0] - nm0);
        float p1 = ex2(s[mt][nb][1] - nm0);
        float p2 = ex2(s[mt][nb][2] - nm1);
        float p3 = ex2(s[mt][nb][3] - nm1);
        sum0 += p0 + p1;
        sum1 += p2 + p3;
        uint2 u01; u01.x = f2tf(p0); u01.y = f2tf(p1);
        uint2 u23; u23.x = f2tf(p2); u23.y = f2tf(p3);
        *(uint2*)&Pw[r * QST + nb * 8 + 2 * tig] = u01;
        *(uint2*)&Pw[(r + 8) * QST + nb * 8 + 2 * tig] = u23;
      }
      sum0 += __shfl_xor_sync(0xffffffffu, sum0, 1);
      sum0 += __shfl_xor_sync(0xffffffffu, sum0, 2);
      sum1 += __shfl_xor_sync(0xffffffffu, sum1, 1);
      sum1 += __shfl_xor_sync(0xffffffffu, sum1, 2);
      lrow[mt][0] = lrow[mt][0] * rf0 + sum0;
      lrow[mt][1] = lrow[mt][1] * rf1 + sum1;
#pragma unroll
      for (int nb = 0; nb < 8; nb++) {
        o[mt][nb][0] *= rf0; o[mt][nb][1] *= rf0;
        o[mt][nb][2] *= rf1; o[mt][nb][3] *= rf1;
      }
    }
    __syncwarp();  // cross-lane P stores visible before a-frag loads

    // ---- O += P V (2 m-tiles share V b-frags) ----
#pragma unroll
    for (int ks = 0; ks < 8; ks++) {
      unsigned a[2][4];
#pragma unroll
      for (int mt = 0; mt < 2; mt++) {
        const int r = mt * 16 + gid;
        a[mt][0] = Pw[r * QST + ks * 8 + tig];
        a[mt][1] = Pw[(r + 8) * QST + ks * 8 + tig];
        a[mt][2] = Pw[r * QST + ks * 8 + tig + 4];
        a[mt][3] = Pw[(r + 8) * QST + ks * 8 + tig + 4];
      }
#pragma unroll
      for (int nb = 0; nb < 8; nb++) {
        unsigned bb[2];
        bb[0] = Vb[(ks * 8 + tig) * VST + nb * 8 + gid];
        bb[1] = Vb[(ks * 8 + tig + 4) * VST + nb * 8 + gid];
        mma8(o[0][nb], a[0], bb);
        mma8(o[1][nb], a[1], bb);
      }
    }

    // ---- publish buffer b^1; guard buffer b for next iter's staging ----
    asm volatile("cp.async.wait_group 0;" ::: "memory");
    __syncthreads();
  }

  // ---- finalize: O / l, write [N, H*D] ----
#pragma unroll
  for (int mt = 0; mt < 2; mt++) {
    const float inv0 = 1.f / lrow[mt][0], inv1 = 1.f / lrow[mt][1];
    const int tok0 = f * P_TOK + qt * 128 + warp * 32 + mt * 16 + gid;
    float* op0 = g_attn + (size_t)tok0 * C_DIM + h * D_DIM;
    float* op1 = op0 + 8 * C_DIM;
#pragma unroll
    for (int nb = 0; nb < 8; nb++) {
      float2 w0, w1;
      w0.x = o[mt][nb][0] * inv0; w0.y = o[mt][nb][1] * inv0;
      w1.x = o[mt][nb][2] * inv1; w1.y = o[mt][nb][3] * inv1;
      *(float2*)&op0[nb * 8 + 2 * tig] = w0;
      *(float2*)&op1[nb * 8 + 2 * tig] = w1;
    }
  }
}

// ---------------------------------------------------------------------------
extern "C" void kernel_launch(void* const* d_in, const int* in_sizes, int n_in,
                              void* d_out, int out_size) {
  const float* x     = (const float*)d_in[0];
  const float* Wqkv  = (const float*)d_in[1];
  const float* bqkv  = (const float*)d_in[2];
  const float* Wproj = (const float*)d_in[3];
  const float* bproj = (const float*)d_in[4];
  const int*   covis = (const int*)d_in[5];
  float* out = (float*)d_out;
  (void)in_sizes; (void)n_in; (void)out_size;

  cudaFuncSetAttribute(attn_kernel, cudaFuncAttributeMaxDynamicSharedMemorySize,
                       ATTN_SMEM);

  gemm_mma<0><<<dim3(QKV_N / 128, N_TOK / 128), 256>>>(x, Wqkv, bqkv,
                                                       nullptr, QKV_N);
  attn_kernel<<<dim3(P_TOK / 128, H_HEADS, S_FR), 128, ATTN_SMEM>>>(covis);
  gemm_mma<1><<<dim3(C_DIM / 128, N_TOK / 128), 256>>>(nullptr, Wproj, bproj,
                                                       out, C_DIM);
}

// round 10
// speedup vs baseline: 1.1818x; 1.0853x over previous
#include <cuda_runtime.h>
#include <math.h>

#define S_FR   16
#define P_TOK  512
#define C_DIM  768
#define H_HEADS 12
#define K_COV  6
#define D_DIM  64
#define N_TOK  8192
#define QKV_N  2304

// Scratch (allocation-free: __device__ globals)
__device__ float g_q[H_HEADS * N_TOK * D_DIM];
__device__ float g_k[H_HEADS * N_TOK * D_DIM];
__device__ float g_v[H_HEADS * N_TOK * D_DIM];
__device__ float g_attn[N_TOK * C_DIM];
__device__ float g_xr[N_TOK * C_DIM];        // tf32-rounded x
__device__ float g_w0[C_DIM * QKV_N];        // tf32-rounded Wqkv
__device__ float g_w1[C_DIM * C_DIM];        // tf32-rounded Wproj

__device__ __forceinline__ unsigned f2tf(float f) {
  unsigned u;
  asm("cvt.rna.tf32.f32 %0, %1;" : "=r"(u) : "f"(f));
  return u;
}
__device__ __forceinline__ float ex2(float x) {
  float y;
  asm("ex2.approx.ftz.f32 %0, %1;" : "=f"(y) : "f"(x));
  return y;
}
__device__ __forceinline__ void mma8(float c[4], const unsigned a[4],
                                     const unsigned b[2]) {
  asm volatile(
      "mma.sync.aligned.m16n8k8.row.col.f32.tf32.tf32.f32 "
      "{%0,%1,%2,%3},{%4,%5,%6,%7},{%8,%9},{%0,%1,%2,%3};\n"
      : "+f"(c[0]), "+f"(c[1]), "+f"(c[2]), "+f"(c[3])
      : "r"(a[0]), "r"(a[1]), "r"(a[2]), "r"(a[3]), "r"(b[0]), "r"(b[1]));
}
__device__ __forceinline__ uint4 tf4(float4 v) {
  uint4 t;
  t.x = f2tf(v.x); t.y = f2tf(v.y); t.z = f2tf(v.z); t.w = f2tf(v.w);
  return t;
}
__device__ __forceinline__ uint4 tf4s(float4 v, float c) {
  uint4 t;
  t.x = f2tf(v.x * c); t.y = f2tf(v.y * c);
  t.z = f2tf(v.z * c); t.w = f2tf(v.w * c);
  return t;
}
__device__ __forceinline__ unsigned smem_u32(const void* p) {
  unsigned a;
  asm("{ .reg .u64 t; cvta.to.shared.u64 t, %1; cvt.u32.u64 %0, t; }"
      : "=r"(a) : "l"(p));
  return a;
}
__device__ __forceinline__ void cp16(unsigned smem, const void* gmem) {
  asm volatile("cp.async.cg.shared.global [%0], [%1], 16;"
               :: "r"(smem), "l"(gmem) : "memory");
}

// ---------------------------------------------------------------------------
// Prep: tf32(rna)-rounded copies of x / Wqkv / Wproj so the GEMMs can
// cp.async raw data (mma's internal truncation becomes a no-op).
// ---------------------------------------------------------------------------
__device__ __forceinline__ float4 rnd4(float4 v) {
  uint4 t = tf4(v);
  float4 o;
  o.x = __uint_as_float(t.x); o.y = __uint_as_float(t.y);
  o.z = __uint_as_float(t.z); o.w = __uint_as_float(t.w);
  return o;
}
__global__ __launch_bounds__(256) void prep_round(
    const float* __restrict__ x, const float* __restrict__ wq,
    const float* __restrict__ wp) {
  const int stride = gridDim.x * blockDim.x;
  const int i0 = blockIdx.x * blockDim.x + threadIdx.x;
  for (int i = i0; i < (N_TOK * C_DIM) / 4; i += stride)
    ((float4*)g_xr)[i] = rnd4(((const float4*)x)[i]);
  for (int i = i0; i < (C_DIM * QKV_N) / 4; i += stride)
    ((float4*)g_w0)[i] = rnd4(((const float4*)wq)[i]);
  for (int i = i0; i < (C_DIM * C_DIM) / 4; i += stride)
    ((float4*)g_w1)[i] = rnd4(((const float4*)wp)[i]);
}

// ---------------------------------------------------------------------------
// TF32 mma GEMM v2: cp.async double-buffered, BK=32, ONE barrier per chunk.
// C[M,Ncols] = A[M,768] * W[768,Ncols] + bias; inputs pre-rounded to tf32.
// MODE 0: A=g_xr, W=g_w0, scatter q/k/v (k/v re-rounded for attn cp.async).
// MODE 1: A=g_attn (pre-rounded at attn finalize), W=g_w1, write d_out.
// As [m][AST=36] (a-frag banks 4*gid+tig), Bs [k][BST=136] (8*tig+gid).
// ---------------------------------------------------------------------------
#define AST 36
#define BST 136
#define GSM_A (128 * AST)          // 4608 words / buffer
#define GSM_B (32 * BST)           // 4352 words / buffer
#define GBUF (GSM_A + GSM_B)       // 8960 words
#define GEMM_SMEM (2 * GBUF * 4)   // 71680 B
#define NKC (C_DIM / 32)           // 24 chunks

template <int MODE>
__global__ __launch_bounds__(256, 2) void gemm_cp(
    const float* __restrict__ bias, float* __restrict__ Cout, int Ncols) {
  extern __shared__ unsigned gsm[];
  const unsigned sbase = smem_u32(gsm);
  const int tid = threadIdx.x;
  const int warp = tid >> 5, lane = tid & 31;
  const int gid = lane >> 2, tig = lane & 3;
  const int wm = warp >> 2, wn = warp & 3;     // 2 x 4 warp grid
  const int bn = blockIdx.x, bm = blockIdx.y;

  const float* Ab =
      ((MODE == 1) ? (const float*)g_attn : (const float*)g_xr) +
      (size_t)(bm * 128) * C_DIM;
  const float* Wb = ((MODE == 1) ? (const float*)g_w1 : (const float*)g_w0) +
                    bn * 128;

  float acc[16][4];
#pragma unroll
  for (int i = 0; i < 16; i++)
#pragma unroll
    for (int j = 0; j < 4; j++) acc[i][j] = 0.f;

  // ---- async staging of one 32-wide k-chunk into buffer `buf` ----
  auto stage = [&](int buf, int k0) {
    const unsigned ab = sbase + buf * (GBUF * 4);
    const unsigned bb = ab + GSM_A * 4;
#pragma unroll
    for (int j = 0; j < 4; j++) {           // A: 128 rows x 32 k
      const int c = tid + 256 * j;
      const int m = c >> 3, kq = (c & 7) << 2;
      cp16(ab + (m * AST + kq) * 4, &Ab[(size_t)m * C_DIM + k0 + kq]);
    }
#pragma unroll
    for (int j = 0; j < 4; j++) {           // W: 32 k x 128 n
      const int c = tid + 256 * j;
      const int k = c >> 5, nq = (c & 31) << 2;
      cp16(bb + (k * BST + nq) * 4, &Wb[(size_t)(k0 + k) * Ncols + nq]);
    }
    asm volatile("cp.async.commit_group;" ::: "memory");
  };

  stage(0, 0);
  asm volatile("cp.async.wait_group 0;" ::: "memory");
  __syncthreads();

  for (int t = 0; t < NKC; t++) {
    const int b = t & 1;
    if (t + 1 < NKC) stage(b ^ 1, (t + 1) * 32);   // overlaps mma below

    const unsigned* As = gsm + b * GBUF;
    const unsigned* Bs = As + GSM_A;
#pragma unroll
    for (int ks = 0; ks < 4; ks++) {
      const int k = ks * 8;
      unsigned af[4][4], bf[4][2];
#pragma unroll
      for (int mt = 0; mt < 4; mt++) {
        const int m = wm * 64 + mt * 16 + gid;
        af[mt][0] = As[m * AST + k + tig];
        af[mt][1] = As[(m + 8) * AST + k + tig];
        af[mt][2] = As[m * AST + k + tig + 4];
        af[mt][3] = As[(m + 8) * AST + k + tig + 4];
      }
#pragma unroll
      for (int nt = 0; nt < 4; nt++) {
        const int n = wn * 32 + nt * 8 + gid;
        bf[nt][0] = Bs[(k + tig) * BST + n];
        bf[nt][1] = Bs[(k + tig + 4) * BST + n];
      }
#pragma unroll
      for (int mt = 0; mt < 4; mt++)
#pragma unroll
        for (int nt = 0; nt < 4; nt++) mma8(acc[mt * 4 + nt], af[mt], bf[nt]);
    }

    asm volatile("cp.async.wait_group 0;" ::: "memory");
    __syncthreads();   // t+1 ready; all readers done with buffer b
  }

  // ---- epilogue: bias + store/scatter ----
#pragma unroll
  for (int mt = 0; mt < 4; mt++) {
#pragma unroll
    for (int nt = 0; nt < 4; nt++) {
      const int row = bm * 128 + wm * 64 + mt * 16 + gid;
      const int col = bn * 128 + wn * 32 + nt * 8 + 2 * tig;
      const float b0 = bias[col], b1 = bias[col + 1];
      float2 lo, hi;
      lo.x = acc[mt * 4 + nt][0] + b0;
      lo.y = acc[mt * 4 + nt][1] + b1;
      hi.x = acc[mt * 4 + nt][2] + b0;
      hi.y = acc[mt * 4 + nt][3] + b1;
      if (MODE == 0) {
        const int which = col / C_DIM;
        const int rem = col - which * C_DIM;
        const int h = rem >> 6, d = rem & 63;
        float* dst = (which == 0) ? g_q : (which == 1 ? g_k : g_v);
        if (which != 0) {  // k/v pre-rounded for attn's raw cp.async
          lo.x = __uint_as_float(f2tf(lo.x));
          lo.y = __uint_as_float(f2tf(lo.y));
          hi.x = __uint_as_float(f2tf(hi.x));
          hi.y = __uint_as_float(f2tf(hi.y));
        }
        *(float2*)&dst[((size_t)h * N_TOK + row) * D_DIM + d] = lo;
        *(float2*)&dst[((size_t)h * N_TOK + row + 8) * D_DIM + d] = hi;
      } else {
        *(float2*)&Cout[(size_t)row * C_DIM + col] = lo;
        *(float2*)&Cout[(size_t)(row + 8) * C_DIM + col] = hi;
      }
    }
  }
}

// ---------------------------------------------------------------------------
// TF32 mma flash attention v5 (round-9, unchanged except: finalize stores
// g_attn pre-rounded to tf32 so gemm1 can cp.async it raw — same values
// gemm1's old staging produced, so output is bitwise identical).
// ---------------------------------------------------------------------------
#define QST 68
#define KST 68
#define VST 72
#define NTILE ((K_COV * P_TOK) / 64)   // 48
#define ATTN_SMEM ((128 * QST + 2 * 64 * KST + 2 * 64 * VST) * 4)

__global__ __launch_bounds__(128, 2) void attn_kernel(
    const int* __restrict__ covis) {
  extern __shared__ unsigned sm[];
  unsigned* Qs = sm;                       // [128][QST]; becomes P after qf
  unsigned* Ks = Qs + 128 * QST;           // [2][64][KST] key-major
  unsigned* Vs = Ks + 2 * 64 * KST;        // [2][64][VST] key-major

  const int tid = threadIdx.x;
  const int warp = tid >> 5, lane = tid & 31;
  const int gid = lane >> 2, tig = lane & 3;
  const int qt = blockIdx.x, h = blockIdx.y, f = blockIdx.z;

  const unsigned ks_base = smem_u32(Ks);
  const unsigned vs_base = smem_u32(Vs);

  const int krow = tid >> 4;               // 0..7
  const int kc4 = (tid & 15) << 2;         // 0,4,...,60

  const float CS = 0.18033688011f;         // 0.125 * log2(e)
  const size_t hbase = (size_t)h * N_TOK;

  // ---- stage Q (fp32 -> tf32, pre-scaled) ----
  const float* qptr = g_q + (hbase + f * P_TOK + qt * 128) * D_DIM;
#pragma unroll
  for (int j = 0; j < 16; j++) {
    int i = j * 128 + tid;
    int row = i >> 4, c4 = (i & 15) << 2;
    *(uint4*)&Qs[row * QST + c4] =
        tf4s(*(const float4*)&qptr[row * D_DIM + c4], CS);
  }

  // ---- cp.async tile 0 into buffer 0 ----
  {
    const int frame = covis[f * K_COV];
    const float* kp = g_k + (hbase + frame * P_TOK) * D_DIM;
    const float* vp = g_v + (hbase + frame * P_TOK) * D_DIM;
#pragma unroll
    for (int j = 0; j < 8; j++) {
      const int row = j * 8 + krow;
      cp16(ks_base + (row * KST + kc4) * 4, &kp[row * D_DIM + kc4]);
      cp16(vs_base + (row * VST + kc4) * 4, &vp[row * D_DIM + kc4]);
    }
    asm volatile("cp.async.commit_group;" ::: "memory");
    asm volatile("cp.async.wait_group 0;" ::: "memory");
  }
  __syncthreads();

  // ---- hoist Q a-fragments into registers (loop-invariant) ----
  const unsigned* Qw = Qs + warp * 32 * QST;
  unsigned qf[2][8][4];
#pragma unroll
  for (int ks = 0; ks < 8; ks++)
#pragma unroll
    for (int mt = 0; mt < 2; mt++) {
      const int r = mt * 16 + gid;
      qf[mt][ks][0] = Qw[r * QST + ks * 8 + tig];
      qf[mt][ks][1] = Qw[(r + 8) * QST + ks * 8 + tig];
      qf[mt][ks][2] = Qw[r * QST + ks * 8 + tig + 4];
      qf[mt][ks][3] = Qw[(r + 8) * QST + ks * 8 + tig + 4];
    }
  unsigned* Pw = (unsigned*)Qw;  // P overlays this warp's (now dead) Q rows

  float o[2][8][4];
#pragma unroll
  for (int mt = 0; mt < 2; mt++)
#pragma unroll
    for (int nb = 0; nb < 8; nb++)
#pragma unroll
      for (int j = 0; j < 4; j++) o[mt][nb][j] = 0.f;
  float mrow[2][2], lrow[2][2];
#pragma unroll
  for (int mt = 0; mt < 2; mt++) {
    mrow[mt][0] = -INFINITY; mrow[mt][1] = -INFINITY;
    lrow[mt][0] = 0.f; lrow[mt][1] = 0.f;
  }

  for (int t = 0; t < NTILE; t++) {
    const int b = t & 1;
    const unsigned* Kb = Ks + b * 64 * KST;
    const unsigned* Vb = Vs + b * 64 * VST;

    // ---- cp.async tile t+1 into buffer b^1 ----
    if (t + 1 < NTILE) {
      const int u = t + 1;
      const int frame = covis[f * K_COV + (u >> 3)];
      const int off = (u & 7) << 6;
      const float* kp = g_k + (hbase + frame * P_TOK + off) * D_DIM;
      const float* vp = g_v + (hbase + frame * P_TOK + off) * D_DIM;
      const unsigned kb = ks_base + (b ^ 1) * (64 * KST * 4);
      const unsigned vb = vs_base + (b ^ 1) * (64 * VST * 4);
#pragma unroll
      for (int j = 0; j < 8; j++) {
        const int row = j * 8 + krow;
        cp16(kb + (row * KST + kc4) * 4, &kp[row * D_DIM + kc4]);
        cp16(vb + (row * VST + kc4) * 4, &vp[row * D_DIM + kc4]);
      }
      asm volatile("cp.async.commit_group;" ::: "memory");
    }

    // ---- S = Q K^T ----
    float s[2][8][4];
#pragma unroll
    for (int mt = 0; mt < 2; mt++)
#pragma unroll
      for (int nb = 0; nb < 8; nb++)
#pragma unroll
        for (int j = 0; j < 4; j++) s[mt][nb][j] = 0.f;
#pragma unroll
    for (int ks = 0; ks < 8; ks++) {
#pragma unroll
      for (int nb = 0; nb < 8; nb++) {
        unsigned bb[2];
        bb[0] = Kb[(nb * 8 + gid) * KST + ks * 8 + tig];
        bb[1] = Kb[(nb * 8 + gid) * KST + ks * 8 + tig + 4];
        mma8(s[0][nb], qf[0][ks], bb);
        mma8(s[1][nb], qf[1][ks], bb);
      }
    }

    // ---- online softmax + P store ----
#pragma unroll
    for (int mt = 0; mt < 2; mt++) {
      float mx0 = -INFINITY, mx1 = -INFINITY;
#pragma unroll
      for (int nb = 0; nb < 8; nb++) {
        mx0 = fmaxf(mx0, fmaxf(s[mt][nb][0], s[mt][nb][1]));
        mx1 = fmaxf(mx1, fmaxf(s[mt][nb][2], s[mt][nb][3]));
      }
      mx0 = fmaxf(mx0, __shfl_xor_sync(0xffffffffu, mx0, 1));
      mx0 = fmaxf(mx0, __shfl_xor_sync(0xffffffffu, mx0, 2));
      mx1 = fmaxf(mx1, __shfl_xor_sync(0xffffffffu, mx1, 1));
      mx1 = fmaxf(mx1, __shfl_xor_sync(0xffffffffu, mx1, 2));
      const float nm0 = fmaxf(mrow[mt][0], mx0);
      const float nm1 = fmaxf(mrow[mt][1], mx1);
      const float rf0 = ex2(mrow[mt][0] - nm0);
      const float rf1 = ex2(mrow[mt][1] - nm1);
      mrow[mt][0] = nm0; mrow[mt][1] = nm1;

      float sum0 = 0.f, sum1 = 0.f;
      const int r = mt * 16 + gid;
#pragma unroll
      for (int nb = 0; nb < 8; nb++) {
        float p0 = ex2(s[mt][nb][0] - nm0);
        float p1 = ex2(s[mt][nb][1] - nm0);
        float p2 = ex2(s[mt][nb][2] - nm1);
        float p3 = ex2(s[mt][nb][3] - nm1);
        sum0 += p0 + p1;
        sum1 += p2 + p3;
        uint2 u01; u01.x = f2tf(p0); u01.y = f2tf(p1);
        uint2 u23; u23.x = f2tf(p2); u23.y = f2tf(p3);
        *(uint2*)&Pw[r * QST + nb * 8 + 2 * tig] = u01;
        *(uint2*)&Pw[(r + 8) * QST + nb * 8 + 2 * tig] = u23;
      }
      sum0 += __shfl_xor_sync(0xffffffffu, sum0, 1);
      sum0 += __shfl_xor_sync(0xffffffffu, sum0, 2);
      sum1 += __shfl_xor_sync(0xffffffffu, sum1, 1);
      sum1 += __shfl_xor_sync(0xffffffffu, sum1, 2);
      lrow[mt][0] = lrow[mt][0] * rf0 + sum0;
      lrow[mt][1] = lrow[mt][1] * rf1 + sum1;
#pragma unroll
      for (int nb = 0; nb < 8; nb++) {
        o[mt][nb][0] *= rf0; o[mt][nb][1] *= rf0;
        o[mt][nb][2] *= rf1; o[mt][nb][3] *= rf1;
      }
    }
    __syncwarp();

    // ---- O += P V ----
#pragma unroll
    for (int ks = 0; ks < 8; ks++) {
      unsigned a[2][4];
#pragma unroll
      for (int mt = 0; mt < 2; mt++) {
        const int r = mt * 16 + gid;
        a[mt][0] = Pw[r * QST + ks * 8 + tig];
        a[mt][1] = Pw[(r + 8) * QST + ks * 8 + tig];
        a[mt][2] = Pw[r * QST + ks * 8 + tig + 4];
        a[mt][3] = Pw[(r + 8) * QST + ks * 8 + tig + 4];
      }
#pragma unroll
      for (int nb = 0; nb < 8; nb++) {
        unsigned bb[2];
        bb[0] = Vb[(ks * 8 + tig) * VST + nb * 8 + gid];
        bb[1] = Vb[(ks * 8 + tig + 4) * VST + nb * 8 + gid];
        mma8(o[0][nb], a[0], bb);
        mma8(o[1][nb], a[1], bb);
      }
    }

    asm volatile("cp.async.wait_group 0;" ::: "memory");
    __syncthreads();
  }

  // ---- finalize: O / l, tf32-round, write [N, H*D] ----
#pragma unroll
  for (int mt = 0; mt < 2; mt++) {
    const float inv0 = 1.f / lrow[mt][0], inv1 = 1.f / lrow[mt][1];
    const int tok0 = f * P_TOK + qt * 128 + warp * 32 + mt * 16 + gid;
    float* op0 = g_attn + (size_t)tok0 * C_DIM + h * D_DIM;
    float* op1 = op0 + 8 * C_DIM;
#pragma unroll
    for (int nb = 0; nb < 8; nb++) {
      float2 w0, w1;
      w0.x = __uint_as_float(f2tf(o[mt][nb][0] * inv0));
      w0.y = __uint_as_float(f2tf(o[mt][nb][1] * inv0));
      w1.x = __uint_as_float(f2tf(o[mt][nb][2] * inv1));
      w1.y = __uint_as_float(f2tf(o[mt][nb][3] * inv1));
      *(float2*)&op0[nb * 8 + 2 * tig] = w0;
      *(float2*)&op1[nb * 8 + 2 * tig] = w1;
    }
  }
}

// ---------------------------------------------------------------------------
extern "C" void kernel_launch(void* const* d_in, const int* in_sizes, int n_in,
                              void* d_out, int out_size) {
  const float* x     = (const float*)d_in[0];
  const float* Wqkv  = (const float*)d_in[1];
  const float* bqkv  = (const float*)d_in[2];
  const float* Wproj = (const float*)d_in[3];
  const float* bproj = (const float*)d_in[4];
  const int*   covis = (const int*)d_in[5];
  float* out = (float*)d_out;
  (void)in_sizes; (void)n_in; (void)out_size;

  cudaFuncSetAttribute(gemm_cp<0>, cudaFuncAttributeMaxDynamicSharedMemorySize,
                       GEMM_SMEM);
  cudaFuncSetAttribute(gemm_cp<1>, cudaFuncAttributeMaxDynamicSharedMemorySize,
                       GEMM_SMEM);
  cudaFuncSetAttribute(attn_kernel, cudaFuncAttributeMaxDynamicSharedMemorySize,
                       ATTN_SMEM);

  prep_round<<<1184, 256>>>(x, Wqkv, Wproj);
  gemm_cp<0><<<dim3(QKV_N / 128, N_TOK / 128), 256, GEMM_SMEM>>>(bqkv, nullptr,
                                                                 QKV_N);
  attn_kernel<<<dim3(P_TOK / 128, H_HEADS, S_FR), 128, ATTN_SMEM>>>(covis);
  gemm_cp<1><<<dim3(C_DIM / 128, N_TOK / 128), 256, GEMM_SMEM>>>(bproj, out,
                                                                 C_DIM);
}

// round 11
// speedup vs baseline: 1.2219x; 1.0340x over previous
#include <cuda_runtime.h>
#include <math.h>

#define S_FR   16
#define P_TOK  512
#define C_DIM  768
#define H_HEADS 12
#define K_COV  6
#define D_DIM  64
#define N_TOK  8192
#define QKV_N  2304

// Scratch (allocation-free: __device__ globals)
__device__ float g_q[H_HEADS * N_TOK * D_DIM];
__device__ float g_k[H_HEADS * N_TOK * D_DIM];
__device__ float g_v[H_HEADS * N_TOK * D_DIM];
__device__ float g_attn[N_TOK * C_DIM];
__device__ float g_xr[N_TOK * C_DIM];        // tf32-rounded x
__device__ float g_w0[C_DIM * QKV_N];        // tf32-rounded Wqkv
__device__ float g_w1[C_DIM * C_DIM];        // tf32-rounded Wproj

__device__ __forceinline__ unsigned f2tf(float f) {
  unsigned u;
  asm("cvt.rna.tf32.f32 %0, %1;" : "=r"(u) : "f"(f));
  return u;
}
__device__ __forceinline__ float ex2(float x) {
  float y;
  asm("ex2.approx.ftz.f32 %0, %1;" : "=f"(y) : "f"(x));
  return y;
}
__device__ __forceinline__ void mma8(float c[4], const unsigned a[4],
                                     const unsigned b[2]) {
  asm volatile(
      "mma.sync.aligned.m16n8k8.row.col.f32.tf32.tf32.f32 "
      "{%0,%1,%2,%3},{%4,%5,%6,%7},{%8,%9},{%0,%1,%2,%3};\n"
      : "+f"(c[0]), "+f"(c[1]), "+f"(c[2]), "+f"(c[3])
      : "r"(a[0]), "r"(a[1]), "r"(a[2]), "r"(a[3]), "r"(b[0]), "r"(b[1]));
}
__device__ __forceinline__ void ldsm4(unsigned r[4], unsigned addr) {
  asm volatile(
      "ldmatrix.sync.aligned.m8n8.x4.shared.b16 {%0,%1,%2,%3}, [%4];"
      : "=r"(r[0]), "=r"(r[1]), "=r"(r[2]), "=r"(r[3]) : "r"(addr));
}
__device__ __forceinline__ uint4 tf4(float4 v) {
  uint4 t;
  t.x = f2tf(v.x); t.y = f2tf(v.y); t.z = f2tf(v.z); t.w = f2tf(v.w);
  return t;
}
__device__ __forceinline__ uint4 tf4s(float4 v, float c) {
  uint4 t;
  t.x = f2tf(v.x * c); t.y = f2tf(v.y * c);
  t.z = f2tf(v.z * c); t.w = f2tf(v.w * c);
  return t;
}
__device__ __forceinline__ unsigned smem_u32(const void* p) {
  unsigned a;
  asm("{ .reg .u64 t; cvta.to.shared.u64 t, %1; cvt.u32.u64 %0, t; }"
      : "=r"(a) : "l"(p));
  return a;
}
__device__ __forceinline__ void cp16(unsigned smem, const void* gmem) {
  asm volatile("cp.async.cg.shared.global [%0], [%1], 16;"
               :: "r"(smem), "l"(gmem) : "memory");
}

// ---------------------------------------------------------------------------
// Prep: tf32(rna)-rounded copies of x / Wqkv / Wproj.
// ---------------------------------------------------------------------------
__device__ __forceinline__ float4 rnd4(float4 v) {
  uint4 t = tf4(v);
  float4 o;
  o.x = __uint_as_float(t.x); o.y = __uint_as_float(t.y);
  o.z = __uint_as_float(t.z); o.w = __uint_as_float(t.w);
  return o;
}
__global__ __launch_bounds__(256) void prep_round(
    const float* __restrict__ x, const float* __restrict__ wq,
    const float* __restrict__ wp) {
  const int stride = gridDim.x * blockDim.x;
  const int i0 = blockIdx.x * blockDim.x + threadIdx.x;
  for (int i = i0; i < (N_TOK * C_DIM) / 4; i += stride)
    ((float4*)g_xr)[i] = rnd4(((const float4*)x)[i]);
  for (int i = i0; i < (C_DIM * QKV_N) / 4; i += stride)
    ((float4*)g_w0)[i] = rnd4(((const float4*)wq)[i]);
  for (int i = i0; i < (C_DIM * C_DIM) / 4; i += stride)
    ((float4*)g_w1)[i] = rnd4(((const float4*)wp)[i]);
}

// ---------------------------------------------------------------------------
// TF32 mma GEMM v2 (round-10, unchanged): cp.async double-buffered, BK=32.
// ---------------------------------------------------------------------------
#define AST 36
#define BST 136
#define GSM_A (128 * AST)
#define GSM_B (32 * BST)
#define GBUF (GSM_A + GSM_B)
#define GEMM_SMEM (2 * GBUF * 4)
#define NKC (C_DIM / 32)

template <int MODE>
__global__ __launch_bounds__(256, 2) void gemm_cp(
    const float* __restrict__ bias, float* __restrict__ Cout, int Ncols) {
  extern __shared__ unsigned gsm[];
  const unsigned sbase = smem_u32(gsm);
  const int tid = threadIdx.x;
  const int warp = tid >> 5, lane = tid & 31;
  const int gid = lane >> 2, tig = lane & 3;
  const int wm = warp >> 2, wn = warp & 3;
  const int bn = blockIdx.x, bm = blockIdx.y;

  const float* Ab =
      ((MODE == 1) ? (const float*)g_attn : (const float*)g_xr) +
      (size_t)(bm * 128) * C_DIM;
  const float* Wb = ((MODE == 1) ? (const float*)g_w1 : (const float*)g_w0) +
                    bn * 128;

  float acc[16][4];
#pragma unroll
  for (int i = 0; i < 16; i++)
#pragma unroll
    for (int j = 0; j < 4; j++) acc[i][j] = 0.f;

  auto stage = [&](int buf, int k0) {
    const unsigned ab = sbase + buf * (GBUF * 4);
    const unsigned bb = ab + GSM_A * 4;
#pragma unroll
    for (int j = 0; j < 4; j++) {
      const int c = tid + 256 * j;
      const int m = c >> 3, kq = (c & 7) << 2;
      cp16(ab + (m * AST + kq) * 4, &Ab[(size_t)m * C_DIM + k0 + kq]);
    }
#pragma unroll
    for (int j = 0; j < 4; j++) {
      const int c = tid + 256 * j;
      const int k = c >> 5, nq = (c & 31) << 2;
      cp16(bb + (k * BST + nq) * 4, &Wb[(size_t)(k0 + k) * Ncols + nq]);
    }
    asm volatile("cp.async.commit_group;" ::: "memory");
  };

  stage(0, 0);
  asm volatile("cp.async.wait_group 0;" ::: "memory");
  __syncthreads();

  for (int t = 0; t < NKC; t++) {
    const int b = t & 1;
    if (t + 1 < NKC) stage(b ^ 1, (t + 1) * 32);

    const unsigned* As = gsm + b * GBUF;
    const unsigned* Bs = As + GSM_A;
#pragma unroll
    for (int ks = 0; ks < 4; ks++) {
      const int k = ks * 8;
      unsigned af[4][4], bf[4][2];
#pragma unroll
      for (int mt = 0; mt < 4; mt++) {
        const int m = wm * 64 + mt * 16 + gid;
        af[mt][0] = As[m * AST + k + tig];
        af[mt][1] = As[(m + 8) * AST + k + tig];
        af[mt][2] = As[m * AST + k + tig + 4];
        af[mt][3] = As[(m + 8) * AST + k + tig + 4];
      }
#pragma unroll
      for (int nt = 0; nt < 4; nt++) {
        const int n = wn * 32 + nt * 8 + gid;
        bf[nt][0] = Bs[(k + tig) * BST + n];
        bf[nt][1] = Bs[(k + tig + 4) * BST + n];
      }
#pragma unroll
      for (int mt = 0; mt < 4; mt++)
#pragma unroll
        for (int nt = 0; nt < 4; nt++) mma8(acc[mt * 4 + nt], af[mt], bf[nt]);
    }

    asm volatile("cp.async.wait_group 0;" ::: "memory");
    __syncthreads();
  }

#pragma unroll
  for (int mt = 0; mt < 4; mt++) {
#pragma unroll
    for (int nt = 0; nt < 4; nt++) {
      const int row = bm * 128 + wm * 64 + mt * 16 + gid;
      const int col = bn * 128 + wn * 32 + nt * 8 + 2 * tig;
      const float b0 = bias[col], b1 = bias[col + 1];
      float2 lo, hi;
      lo.x = acc[mt * 4 + nt][0] + b0;
      lo.y = acc[mt * 4 + nt][1] + b1;
      hi.x = acc[mt * 4 + nt][2] + b0;
      hi.y = acc[mt * 4 + nt][3] + b1;
      if (MODE == 0) {
        const int which = col / C_DIM;
        const int rem = col - which * C_DIM;
        const int h = rem >> 6, d = rem & 63;
        float* dst = (which == 0) ? g_q : (which == 1 ? g_k : g_v);
        if (which != 0) {
          lo.x = __uint_as_float(f2tf(lo.x));
          lo.y = __uint_as_float(f2tf(lo.y));
          hi.x = __uint_as_float(f2tf(hi.x));
          hi.y = __uint_as_float(f2tf(hi.y));
        }
        *(float2*)&dst[((size_t)h * N_TOK + row) * D_DIM + d] = lo;
        *(float2*)&dst[((size_t)h * N_TOK + row + 8) * D_DIM + d] = hi;
      } else {
        *(float2*)&Cout[(size_t)row * C_DIM + col] = lo;
        *(float2*)&Cout[(size_t)(row + 8) * C_DIM + col] = hi;
      }
    }
  }
}

// ---------------------------------------------------------------------------
// TF32 mma flash attention v6: round-9 structure + ldmatrix.x4 for K b-frags
// (128 LDS -> 32 LDSM) and P a-frags (64 LDS -> 16 LDSM). Same bytes, same
// bits, 1/4 the issue slots for fragment loads.
// ---------------------------------------------------------------------------
#define QST 68
#define KST 68
#define VST 72
#define NTILE ((K_COV * P_TOK) / 64)   // 48
#define ATTN_SMEM ((128 * QST + 2 * 64 * KST + 2 * 64 * VST) * 4)

__global__ __launch_bounds__(128, 2) void attn_kernel(
    const int* __restrict__ covis) {
  extern __shared__ unsigned sm[];
  unsigned* Qs = sm;                       // [128][QST]; becomes P after qf
  unsigned* Ks = Qs + 128 * QST;           // [2][64][KST] key-major
  unsigned* Vs = Ks + 2 * 64 * KST;        // [2][64][VST] key-major

  const int tid = threadIdx.x;
  const int warp = tid >> 5, lane = tid & 31;
  const int gid = lane >> 2, tig = lane & 3;
  const int qt = blockIdx.x, h = blockIdx.y, f = blockIdx.z;

  const unsigned ks_base = smem_u32(Ks);
  const unsigned vs_base = smem_u32(Vs);

  const int krow = tid >> 4;               // 0..7
  const int kc4 = (tid & 15) << 2;         // 0,4,...,60

  const float CS = 0.18033688011f;         // 0.125 * log2(e)
  const size_t hbase = (size_t)h * N_TOK;

  // ldmatrix per-lane static byte offsets
  // K tiles: {nb rows/col k, nb/col k+4, nb+1/col k, nb+1/col k+4}
  const unsigned kls =
      ((((lane >> 4) * 8 + (lane & 7)) * KST + ((lane >> 3) & 1) * 4)) * 4;
  // P tiles: {rows r, rows r+8, rows r/col+4, rows r+8/col+4}
  const unsigned pls =
      (((((lane >> 3) & 1) * 8 + (lane & 7)) * QST + (lane >> 4) * 4)) * 4;

  // ---- stage Q (fp32 -> tf32, pre-scaled) ----
  const float* qptr = g_q + (hbase + f * P_TOK + qt * 128) * D_DIM;
#pragma unroll
  for (int j = 0; j < 16; j++) {
    int i = j * 128 + tid;
    int row = i >> 4, c4 = (i & 15) << 2;
    *(uint4*)&Qs[row * QST + c4] =
        tf4s(*(const float4*)&qptr[row * D_DIM + c4], CS);
  }

  // ---- cp.async tile 0 into buffer 0 ----
  {
    const int frame = covis[f * K_COV];
    const float* kp = g_k + (hbase + frame * P_TOK) * D_DIM;
    const float* vp = g_v + (hbase + frame * P_TOK) * D_DIM;
#pragma unroll
    for (int j = 0; j < 8; j++) {
      const int row = j * 8 + krow;
      cp16(ks_base + (row * KST + kc4) * 4, &kp[row * D_DIM + kc4]);
      cp16(vs_base + (row * VST + kc4) * 4, &vp[row * D_DIM + kc4]);
    }
    asm volatile("cp.async.commit_group;" ::: "memory");
    asm volatile("cp.async.wait_group 0;" ::: "memory");
  }
  __syncthreads();

  // ---- hoist Q a-fragments into registers (loop-invariant) ----
  const unsigned* Qw = Qs + warp * 32 * QST;
  unsigned qf[2][8][4];
#pragma unroll
  for (int ks = 0; ks < 8; ks++)
#pragma unroll
    for (int mt = 0; mt < 2; mt++) {
      const int r = mt * 16 + gid;
      qf[mt][ks][0] = Qw[r * QST + ks * 8 + tig];
      qf[mt][ks][1] = Qw[(r + 8) * QST + ks * 8 + tig];
      qf[mt][ks][2] = Qw[r * QST + ks * 8 + tig + 4];
      qf[mt][ks][3] = Qw[(r + 8) * QST + ks * 8 + tig + 4];
    }
  unsigned* Pw = (unsigned*)Qw;            // P overlays this warp's Q rows
  const unsigned p_lm = smem_u32(Pw) + pls;

  float o[2][8][4];
#pragma unroll
  for (int mt = 0; mt < 2; mt++)
#pragma unroll
    for (int nb = 0; nb < 8; nb++)
#pragma unroll
      for (int j = 0; j < 4; j++) o[mt][nb][j] = 0.f;
  float mrow[2][2], lrow[2][2];
#pragma unroll
  for (int mt = 0; mt < 2; mt++) {
    mrow[mt][0] = -INFINITY; mrow[mt][1] = -INFINITY;
    lrow[mt][0] = 0.f; lrow[mt][1] = 0.f;
  }

  for (int t = 0; t < NTILE; t++) {
    const int b = t & 1;
    const unsigned* Vb = Vs + b * 64 * VST;
    const unsigned kb_lm = ks_base + b * (64 * KST * 4) + kls;

    // ---- cp.async tile t+1 into buffer b^1 ----
    if (t + 1 < NTILE) {
      const int u = t + 1;
      const int frame = covis[f * K_COV + (u >> 3)];
      const int off = (u & 7) << 6;
      const float* kp = g_k + (hbase + frame * P_TOK + off) * D_DIM;
      const float* vp = g_v + (hbase + frame * P_TOK + off) * D_DIM;
      const unsigned kb = ks_base + (b ^ 1) * (64 * KST * 4);
      const unsigned vb = vs_base + (b ^ 1) * (64 * VST * 4);
#pragma unroll
      for (int j = 0; j < 8; j++) {
        const int row = j * 8 + krow;
        cp16(kb + (row * KST + kc4) * 4, &kp[row * D_DIM + kc4]);
        cp16(vb + (row * VST + kc4) * 4, &vp[row * D_DIM + kc4]);
      }
      asm volatile("cp.async.commit_group;" ::: "memory");
    }

    // ---- S = Q K^T : K b-frags via ldmatrix.x4 (2 nb per LDSM) ----
    float s[2][8][4];
#pragma unroll
    for (int mt = 0; mt < 2; mt++)
#pragma unroll
      for (int nb = 0; nb < 8; nb++)
#pragma unroll
        for (int j = 0; j < 4; j++) s[mt][nb][j] = 0.f;
#pragma unroll
    for (int ks = 0; ks < 8; ks++) {
#pragma unroll
      for (int nbp = 0; nbp < 4; nbp++) {
        unsigned kr[4];
        ldsm4(kr, kb_lm + (nbp * 16 * KST + ks * 8) * 4);
        mma8(s[0][2 * nbp], qf[0][ks], &kr[0]);
        mma8(s[1][2 * nbp], qf[1][ks], &kr[0]);
        mma8(s[0][2 * nbp + 1], qf[0][ks], &kr[2]);
        mma8(s[1][2 * nbp + 1], qf[1][ks], &kr[2]);
      }
    }

    // ---- online softmax (base-2; Q pre-scaled) + P store ----
#pragma unroll
    for (int mt = 0; mt < 2; mt++) {
      float mx0 = -INFINITY, mx1 = -INFINITY;
#pragma unroll
      for (int nb = 0; nb < 8; nb++) {
        mx0 = fmaxf(mx0, fmaxf(s[mt][nb][0], s[mt][nb][1]));
        mx1 = fmaxf(mx1, fmaxf(s[mt][nb][2], s[mt][nb][3]));
      }
      mx0 = fmaxf(mx0, __shfl_xor_sync(0xffffffffu, mx0, 1));
      mx0 = fmaxf(mx0, __shfl_xor_sync(0xffffffffu, mx0, 2));
      mx1 = fmaxf(mx1, __shfl_xor_sync(0xffffffffu, mx1, 1));
      mx1 = fmaxf(mx1, __shfl_xor_sync(0xffffffffu, mx1, 2));
      const float nm0 = fmaxf(mrow[mt][0], mx0);
      const float nm1 = fmaxf(mrow[mt][1], mx1);
      const float rf0 = ex2(mrow[mt][0] - nm0);
      const float rf1 = ex2(mrow[mt][1] - nm1);
      mrow[mt][0] = nm0; mrow[mt][1] = nm1;

      float sum0 = 0.f, sum1 = 0.f;
      const int r = mt * 16 + gid;
#pragma unroll
      for (int nb = 0; nb < 8; nb++) {
        float p0 = ex2(s[mt][nb][0] - nm0);
        float p1 = ex2(s[mt][nb][1] - nm0);
        float p2 = ex2(s[mt][nb][2] - nm1);
        float p3 = ex2(s[mt][nb][3] - nm1);
        sum0 += p0 + p1;
        sum1 += p2 + p3;
        uint2 u01; u01.x = f2tf(p0); u01.y = f2tf(p1);
        uint2 u23; u23.x = f2tf(p2); u23.y = f2tf(p3);
        *(uint2*)&Pw[r * QST + nb * 8 + 2 * tig] = u01;
        *(uint2*)&Pw[(r + 8) * QST + nb * 8 + 2 * tig] = u23;
      }
      sum0 += __shfl_xor_sync(0xffffffffu, sum0, 1);
      sum0 += __shfl_xor_sync(0xffffffffu, sum0, 2);
      sum1 += __shfl_xor_sync(0xffffffffu, sum1, 1);
      sum1 += __shfl_xor_sync(0xffffffffu, sum1, 2);
      lrow[mt][0] = lrow[mt][0] * rf0 + sum0;
      lrow[mt][1] = lrow[mt][1] * rf1 + sum1;
#pragma unroll
      for (int nb = 0; nb < 8; nb++) {
        o[mt][nb][0] *= rf0; o[mt][nb][1] *= rf0;
        o[mt][nb][2] *= rf1; o[mt][nb][3] *= rf1;
      }
    }
    __syncwarp();  // cross-lane P stores visible before ldmatrix reads

    // ---- O += P V : P a-frags via ldmatrix.x4 (one per mt per ks) ----
#pragma unroll
    for (int ks = 0; ks < 8; ks++) {
      unsigned a0[4], a1[4];
      ldsm4(a0, p_lm + (ks * 8) * 4);
      ldsm4(a1, p_lm + (16 * QST + ks * 8) * 4);
#pragma unroll
      for (int nb = 0; nb < 8; nb++) {
        unsigned bb[2];
        bb[0] = Vb[(ks * 8 + tig) * VST + nb * 8 + gid];
        bb[1] = Vb[(ks * 8 + tig + 4) * VST + nb * 8 + gid];
        mma8(o[0][nb], a0, bb);
        mma8(o[1][nb], a1, bb);
      }
    }

    asm volatile("cp.async.wait_group 0;" ::: "memory");
    __syncthreads();
  }

  // ---- finalize: O / l, tf32-round, write [N, H*D] ----
#pragma unroll
  for (int mt = 0; mt < 2; mt++) {
    const float inv0 = 1.f / lrow[mt][0], inv1 = 1.f / lrow[mt][1];
    const int tok0 = f * P_TOK + qt * 128 + warp * 32 + mt * 16 + gid;
    float* op0 = g_attn + (size_t)tok0 * C_DIM + h * D_DIM;
    float* op1 = op0 + 8 * C_DIM;
#pragma unroll
    for (int nb = 0; nb < 8; nb++) {
      float2 w0, w1;
      w0.x = __uint_as_float(f2tf(o[mt][nb][0] * inv0));
      w0.y = __uint_as_float(f2tf(o[mt][nb][1] * inv0));
      w1.x = __uint_as_float(f2tf(o[mt][nb][2] * inv1));
      w1.y = __uint_as_float(f2tf(o[mt][nb][3] * inv1));
      *(float2*)&op0[nb * 8 + 2 * tig] = w0;
      *(float2*)&op1[nb * 8 + 2 * tig] = w1;
    }
  }
}

// ---------------------------------------------------------------------------
extern "C" void kernel_launch(void* const* d_in, const int* in_sizes, int n_in,
                              void* d_out, int out_size) {
  const float* x     = (const float*)d_in[0];
  const float* Wqkv  = (const float*)d_in[1];
  const float* bqkv  = (const float*)d_in[2];
  const float* Wproj = (const float*)d_in[3];
  const float* bproj = (const float*)d_in[4];
  const int*   covis = (const int*)d_in[5];
  float* out = (float*)d_out;
  (void)in_sizes; (void)n_in; (void)out_size;

  cudaFuncSetAttribute(gemm_cp<0>, cudaFuncAttributeMaxDynamicSharedMemorySize,
                       GEMM_SMEM);
  cudaFuncSetAttribute(gemm_cp<1>, cudaFuncAttributeMaxDynamicSharedMemorySize,
                       GEMM_SMEM);
  cudaFuncSetAttribute(attn_kernel, cudaFuncAttributeMaxDynamicSharedMemorySize,
                       ATTN_SMEM);

  prep_round<<<1184, 256>>>(x, Wqkv, Wproj);
  gemm_cp<0><<<dim3(QKV_N / 128, N_TOK / 128), 256, GEMM_SMEM>>>(bqkv, nullptr,
                                                                 QKV_N);
  attn_kernel<<<dim3(P_TOK / 128, H_HEADS, S_FR), 128, ATTN_SMEM>>>(covis);
  gemm_cp<1><<<dim3(C_DIM / 128, N_TOK / 128), 256, GEMM_SMEM>>>(bproj, out,
                                                                 C_DIM);
}